// round 15
// baseline (speedup 1.0000x reference)
#include <cuda_runtime.h>

#define BB 4
#define NN 8192
#define DD 32
#define KNB 16
#define M0 32
#define M1 32
#define M2 64
#define LEAKY 0.1f

#define BINS 1024
#define XMIN (-16.0f)
#define XRANGE 32.0f
#define BINW (XRANGE / (float)BINS)
#define MARG 2e-3f

#define STILE 256
#define NT (NN / STILE)      // 32 tiles per batch
#define RINGN 16
#define KBLK 128             // 32 queries x 4 lanes

__device__ float4 g_xyzw[BB * NN];
__device__ float  g_feat[BB * NN * M0];
__device__ int    g_idx[BB * NN * KNB];

__device__ int    g_bincnt[BB * BINS];
__device__ int    g_bincur[BB * BINS];
__device__ float4 g_s4[BB * NN];
__device__ int    g_sidx[BB * NN];

__device__ __forceinline__ float lrelu(float x) { return x > 0.f ? x : LEAKY * x; }

__device__ __forceinline__ int xbin(float x) {
    int bn = (int)((x - XMIN) * ((float)BINS / XRANGE));
    return min(max(bn, 0), BINS - 1);
}

__device__ __forceinline__ unsigned long long pk2(float lo, float hi) {
    unsigned long long r;
    asm("mov.b64 %0, {%1, %2};" : "=l"(r) : "f"(lo), "f"(hi));
    return r;
}
__device__ __forceinline__ void upk2(unsigned long long v, float& lo, float& hi) {
    asm("mov.b64 {%0, %1}, %2;" : "=f"(lo), "=f"(hi) : "l"(v));
}
__device__ __forceinline__ unsigned long long fma2(unsigned long long a,
                                                   unsigned long long b,
                                                   unsigned long long c) {
    unsigned long long d;
    asm("fma.rn.f32x2 %0, %1, %2, %3;" : "=l"(d) : "l"(a), "l"(b), "l"(c));
    return d;
}

// ---------------------------------------------------------------------------
// Kernel 0: zero histogram counters
// ---------------------------------------------------------------------------
__global__ void init_kernel(void) {
    int i = blockIdx.x * 1024 + threadIdx.x;
    if (i < BB * BINS) g_bincnt[i] = 0;
}

// ---------------------------------------------------------------------------
// Kernel 1: pack xyz; feat = W0[:,3:] @ points; histogram x into bins.
// ---------------------------------------------------------------------------
__global__ void prep_kernel(const float* __restrict__ xyz,
                            const float* __restrict__ points,
                            const float* __restrict__ W0) {
    __shared__ __align__(16) float wfT[DD][M0];
    int tid = threadIdx.x;
    for (int i = tid; i < DD * M0; i += 128) {
        int c = i / M0, o = i % M0;
        wfT[c][o] = W0[o * 35 + 3 + c];
    }
    __syncthreads();

    int gq = blockIdx.x * 128 + tid;
    int b = gq / NN, n = gq % NN;

    const float* xb = xyz + (size_t)b * 3 * NN;
    float x = xb[n], y = xb[NN + n], z = xb[2 * NN + n];
    float sq = fmaf(x, x, fmaf(y, y, z * z));
    g_xyzw[gq] = make_float4(x, y, z, sq);

    atomicAdd(&g_bincnt[b * BINS + xbin(x)], 1);

    float acc[M0];
#pragma unroll
    for (int o = 0; o < M0; o++) acc[o] = 0.f;

    const float* pb = points + (size_t)b * DD * NN + n;
#pragma unroll 4
    for (int c = 0; c < DD; c++) {
        float p = pb[(size_t)c * NN];
        const float4* w4 = (const float4*)wfT[c];
#pragma unroll
        for (int o4 = 0; o4 < M0 / 4; o4++) {
            float4 w = w4[o4];
            acc[o4 * 4 + 0] = fmaf(w.x, p, acc[o4 * 4 + 0]);
            acc[o4 * 4 + 1] = fmaf(w.y, p, acc[o4 * 4 + 1]);
            acc[o4 * 4 + 2] = fmaf(w.z, p, acc[o4 * 4 + 2]);
            acc[o4 * 4 + 3] = fmaf(w.w, p, acc[o4 * 4 + 3]);
        }
    }
    float4* fo = (float4*)(g_feat + (size_t)gq * M0);
#pragma unroll
    for (int o4 = 0; o4 < M0 / 4; o4++)
        fo[o4] = make_float4(acc[o4 * 4 + 0], acc[o4 * 4 + 1],
                             acc[o4 * 4 + 2], acc[o4 * 4 + 3]);
}

// ---------------------------------------------------------------------------
// Kernel 2: parallel per-batch prefix scan
// ---------------------------------------------------------------------------
__global__ void prefix_kernel(void) {
    __shared__ int s[BINS];
    int b = blockIdx.x, t = threadIdx.x;
    int mine = g_bincnt[b * BINS + t];
    s[t] = mine;
    __syncthreads();
    for (int off = 1; off < BINS; off <<= 1) {
        int v = (t >= off) ? s[t - off] : 0;
        __syncthreads();
        s[t] += v;
        __syncthreads();
    }
    g_bincur[b * BINS + t] = s[t] - mine;
}

// ---------------------------------------------------------------------------
// Kernel 3: scatter points into x-bin-sorted arrays
// ---------------------------------------------------------------------------
__global__ void scatter_kernel(void) {
    int gq = blockIdx.x * 256 + threadIdx.x;
    int b = gq / NN, n = gq % NN;
    float4 p = g_xyzw[gq];
    int pos = atomicAdd(&g_bincur[b * BINS + xbin(p.x)], 1);
    g_s4[b * NN + pos] = p;
    g_sidx[b * NN + pos] = n;
}

// ---------------------------------------------------------------------------
// kNN consolidation (lex keys; original idx via resident sidx tile)
// ---------------------------------------------------------------------------
__device__ __forceinline__ void consolidate(unsigned long long (&slot)[KNB],
                                            unsigned long long& worstkey,
                                            float& worst_d, int& cnt,
                                            unsigned long long (*ring)[KBLK],
                                            const int* stile, int tid) {
#pragma unroll 1
    for (int i = 0; i < cnt; i++) {
        unsigned long long e = ring[i][tid];
        unsigned db = (unsigned)(e >> 32);
        unsigned orig = (unsigned)stile[(unsigned)e & (STILE - 1)];
        unsigned msk = ((unsigned)((int)db >> 31)) | 0x80000000u;
        unsigned long long key = ((unsigned long long)(db ^ msk) << 32) | orig;
        if (key < worstkey) {
#pragma unroll
            for (int m = 0; m < KNB; m++)
                slot[m] = (slot[m] == worstkey) ? key : slot[m];
            unsigned long long w = slot[0];
#pragma unroll
            for (int m = 1; m < KNB; m++) w = (slot[m] > w) ? slot[m] : w;
            worstkey = w;
        }
    }
    cnt = 0;
    unsigned k32 = (unsigned)(worstkey >> 32);
    unsigned bits = (k32 & 0x80000000u) ? (k32 ^ 0x80000000u) : ~k32;
    worst_d = __uint_as_float(bits);
}

// ---------------------------------------------------------------------------
// Kernel 4: sorted-window kNN. block 128 = 32 consecutive sorted queries x
// 4 lanes. Tile edges PRECOMPUTED into smem once (edge checks become LDS
// reads; deletes 2 syncs + 1 serial L2 LDG per expansion round).
// grid (N/32, B).
// ---------------------------------------------------------------------------
__global__ void __launch_bounds__(KBLK) knnt_kernel(void) {
    __shared__ __align__(16) float4 tile[STILE];
    __shared__ int stile[STILE];
    __shared__ unsigned long long ring[RINGN][KBLK];
    __shared__ float edgeFirst[NT];   // s4[t*STILE].x
    __shared__ float edgeLast[NT];    // s4[t*STILE + STILE-1].x

    int tid = threadIdx.x;
    int b = blockIdx.y;
    int r = tid & 3;
    int rank = blockIdx.x * 32 + (tid >> 2);

    const float4* __restrict__ s4 = g_s4 + (size_t)b * NN;
    const int* __restrict__ sidx = g_sidx + (size_t)b * NN;

    // precompute all tile edges (one pass, one sync)
    if (tid < NT) edgeFirst[tid] = s4[tid * STILE].x;
    else if (tid < 2 * NT)
        edgeLast[tid - NT] = s4[(tid - NT) * STILE + STILE - 1].x;

    float4 qf = s4[rank];
    int qorig = sidx[rank];
    float nqx = -2.f * qf.x, nqy = -2.f * qf.y, nqz = -2.f * qf.z;
    float qw = qf.w;

    unsigned long long slot[KNB];
#pragma unroll
    for (int m = 0; m < KNB; m++)
        slot[m] = 0xFF80000000000000ull | (unsigned)m;
    unsigned long long worstkey = 0xFF80000000000000ull | (KNB - 1);
    float worst_d = __int_as_float(0x7F800000);
    float tp = __int_as_float(0x7F800000);
    int cnt = 0;

    int T0 = (blockIdx.x * 32) / STILE;
    int tR = T0, tL = T0 - 1;
    bool myRightDone = false, myLeftDone = false;
    bool firstTile = true;

    __syncthreads();   // edges visible

    for (;;) {
        int doScan = -1;

        if (tR < NT) {
            bool prune = false;
            if (!firstTile) {
                float dxlo = edgeFirst[tR] - BINW - qf.x;
                prune = (dxlo > 0.f) && (dxlo * dxlo > tp + MARG);
            }
            myRightDone = myRightDone || prune;
            if (__syncthreads_and(myRightDone ? 1 : 0)) tR = NT;
            else { doScan = tR; tR++; }
            firstTile = false;
        }
        if (doScan < 0 && tL >= 0) {
            float dxlo = qf.x - (edgeLast[tL] + BINW);
            bool prune = (dxlo > 0.f) && (dxlo * dxlo > tp + MARG);
            myLeftDone = myLeftDone || prune;
            if (__syncthreads_and(myLeftDone ? 1 : 0)) tL = -1;
            else { doScan = tL; tL--; }
        }
        if (doScan < 0) {
            if (tR >= NT && tL < 0) break;
            continue;
        }

        __syncthreads();
        {
            const float4* src = s4 + doScan * STILE;
            const int* si = sidx + doScan * STILE;
            for (int i = tid; i < STILE; i += KBLK) {
                tile[i] = src[i];
                stile[i] = si[i];
            }
        }
        __syncthreads();

#pragma unroll 1
        for (int j0 = 0; j0 < STILE; j0 += 32) {
#pragma unroll
            for (int u = 0; u < 8; u++) {
                int jl = j0 + u * 4 + r;
                float4 c = tile[jl];
                float d = fmaf(nqx, c.x,
                          fmaf(nqy, c.y, fmaf(nqz, c.z, qw + c.w)));
                ring[cnt][tid] =
                    ((unsigned long long)__float_as_uint(d) << 32) |
                    (unsigned)jl;
                cnt += (d <= tp) ? 1 : 0;
            }
            if (__ballot_sync(0xffffffffu, cnt >= 9)) {
                consolidate(slot, worstkey, worst_d, cnt, ring, stile, tid);
                float tt = fminf(worst_d,
                                 __shfl_xor_sync(0xffffffffu, worst_d, 1));
                tt = fminf(tt, __shfl_xor_sync(0xffffffffu, tt, 2));
                tp = tt;
            }
        }
        if (__ballot_sync(0xffffffffu, cnt > 0)) {
            consolidate(slot, worstkey, worst_d, cnt, ring, stile, tid);
            float tt = fminf(worst_d,
                             __shfl_xor_sync(0xffffffffu, worst_d, 1));
            tt = fminf(tt, __shfl_xor_sync(0xffffffffu, tt, 2));
            tp = tt;
        }
    }

    // bitonic sort own 16 ascending
#pragma unroll
    for (int k = 2; k <= KNB; k <<= 1) {
#pragma unroll
        for (int jj = k >> 1; jj > 0; jj >>= 1) {
#pragma unroll
            for (int ii = 0; ii < KNB; ii++) {
                int p = ii ^ jj;
                if (p > ii) {
                    bool up = ((ii & k) == 0);
                    unsigned long long a = slot[ii], bb2 = slot[p];
                    bool sw = (a > bb2) != up;
                    slot[ii] = sw ? bb2 : a;
                    slot[p] = sw ? a : bb2;
                }
            }
        }
    }

    // 2 butterfly merge rounds across the 4 lanes
#pragma unroll
    for (int step = 1; step <= 2; step <<= 1) {
        unsigned long long other[KNB];
#pragma unroll
        for (int ii = 0; ii < KNB; ii++)
            other[ii] = __shfl_xor_sync(0xffffffffu, slot[ii], step);
        unsigned long long c[KNB];
#pragma unroll
        for (int ii = 0; ii < KNB; ii++) {
            unsigned long long bv = other[KNB - 1 - ii];
            c[ii] = (slot[ii] < bv) ? slot[ii] : bv;
        }
#pragma unroll
        for (int jj = KNB / 2; jj > 0; jj >>= 1) {
#pragma unroll
            for (int ii = 0; ii < KNB; ii++) {
                if ((ii & jj) == 0) {
                    int p = ii | jj;
                    unsigned long long a = c[ii], bb2 = c[p];
                    bool sw = (a > bb2);
                    c[ii] = sw ? bb2 : a;
                    c[p] = sw ? a : bb2;
                }
            }
        }
#pragma unroll
        for (int ii = 0; ii < KNB; ii++) slot[ii] = c[ii];
    }

    int4* op = (int4*)(g_idx + ((size_t)b * NN + qorig) * KNB + 4 * r);
    *op = make_int4((int)(unsigned)slot[4 * r + 0],
                    (int)(unsigned)slot[4 * r + 1],
                    (int)(unsigned)slot[4 * r + 2],
                    (int)(unsigned)slot[4 * r + 3]);
}

// ---------------------------------------------------------------------------
// Kernel 5: gather + MLP + max. block 128 = 16 queries x 8 lanes; each lane
// handles 2 neighbors (k, k+8). Layers 0, 1 AND 2 all share their smem
// weight loads across both neighbors (halves layer-0/1 LDS vs R13/R14).
// Named register arrays only (no dynamic indexing).
// ---------------------------------------------------------------------------
__global__ void __launch_bounds__(128) mlp_kernel(const float* __restrict__ W0,
                                                  const float* __restrict__ W1,
                                                  const float* __restrict__ W2,
                                                  float* __restrict__ out) {
    __shared__ __align__(16) float w0x[M0][4];
    __shared__ __align__(16) unsigned long long w1p[M0][M1 / 2];
    __shared__ __align__(16) unsigned long long w2p[M1][M2 / 2];
    __shared__ float stage[16][M2];

    int tid = threadIdx.x;
    for (int i = tid; i < M0 * 4; i += 128) {
        int o = i / 4, c = i % 4;
        w0x[o][c] = (c < 3) ? W0[o * 35 + c] : 0.f;
    }
    for (int i = tid; i < M0 * (M1 / 2); i += 128) {
        int c = i / (M1 / 2), p = i % (M1 / 2);
        w1p[c][p] = pk2(W1[(2 * p) * M0 + c], W1[(2 * p + 1) * M0 + c]);
    }
    for (int i = tid; i < M1 * (M2 / 2); i += 128) {
        int c = i / (M2 / 2), p = i % (M2 / 2);
        w2p[c][p] = pk2(W2[(2 * p) * M1 + c], W2[(2 * p + 1) * M1 + c]);
    }
    __syncthreads();

    int g = tid >> 3, k = tid & 7;          // 16 queries x 8 lanes
    int gq = blockIdx.x * 16 + g;
    int b = gq / NN;
    float4 qf = g_xyzw[gq];

    int ja = g_idx[(size_t)gq * KNB + k];
    int jb = g_idx[(size_t)gq * KNB + k + 8];
    float4 cfa = g_xyzw[b * NN + ja];
    float4 cfb = g_xyzw[b * NN + jb];
    float rxa = cfa.x - qf.x, rya = cfa.y - qf.y, rza = cfa.z - qf.z;
    float rxb = cfb.x - qf.x, ryb = cfb.y - qf.y, rzb = cfb.z - qf.z;

    // ---- layer 0 (shared w0x loads) ----
    float h0a[M0], h0b[M0];
    const float4* fga = (const float4*)(g_feat + ((size_t)b * NN + ja) * M0);
    const float4* fgb = (const float4*)(g_feat + ((size_t)b * NN + jb) * M0);
#pragma unroll
    for (int o4 = 0; o4 < M0 / 4; o4++) {
        float4 fa = fga[o4];
        float4 fb = fgb[o4];
        float fva[4] = {fa.x, fa.y, fa.z, fa.w};
        float fvb[4] = {fb.x, fb.y, fb.z, fb.w};
#pragma unroll
        for (int u = 0; u < 4; u++) {
            float4 w = *(const float4*)w0x[o4 * 4 + u];
            h0a[o4 * 4 + u] =
                lrelu(fmaf(w.x, rxa, fmaf(w.y, rya, fmaf(w.z, rza, fva[u]))));
            h0b[o4 * 4 + u] =
                lrelu(fmaf(w.x, rxb, fmaf(w.y, ryb, fmaf(w.z, rzb, fvb[u]))));
        }
    }

    // ---- layer 1 (shared w1p loads, both neighbors per c) ----
    unsigned long long acc1a[M1 / 2], acc1b[M1 / 2];
#pragma unroll
    for (int p = 0; p < M1 / 2; p++) { acc1a[p] = 0ull; acc1b[p] = 0ull; }
#pragma unroll
    for (int c = 0; c < M0; c++) {
        unsigned long long hpa = pk2(h0a[c], h0a[c]);
        unsigned long long hpb = pk2(h0b[c], h0b[c]);
        const ulonglong2* wv = (const ulonglong2*)w1p[c];
#pragma unroll
        for (int p2 = 0; p2 < M1 / 4; p2++) {
            ulonglong2 w = wv[p2];
            acc1a[2 * p2 + 0] = fma2(w.x, hpa, acc1a[2 * p2 + 0]);
            acc1a[2 * p2 + 1] = fma2(w.y, hpa, acc1a[2 * p2 + 1]);
            acc1b[2 * p2 + 0] = fma2(w.x, hpb, acc1b[2 * p2 + 0]);
            acc1b[2 * p2 + 1] = fma2(w.y, hpb, acc1b[2 * p2 + 1]);
        }
    }
    float h1a[M1], h1b[M1];
#pragma unroll
    for (int p = 0; p < M1 / 2; p++) {
        float a, bv;
        upk2(acc1a[p], a, bv);
        h1a[2 * p + 0] = lrelu(a);
        h1a[2 * p + 1] = lrelu(bv);
        upk2(acc1b[p], a, bv);
        h1b[2 * p + 0] = lrelu(a);
        h1b[2 * p + 1] = lrelu(bv);
    }

    // ---- layer 2 (shared w2p loads) + pairwise max + 3-step shfl max ----
#pragma unroll 1
    for (int ch = 0; ch < M2 / 8; ch++) {
        unsigned long long a01 = 0ull, a23 = 0ull, a45 = 0ull, a67 = 0ull;
        unsigned long long b01 = 0ull, b23 = 0ull, b45 = 0ull, b67 = 0ull;
#pragma unroll
        for (int c = 0; c < M1; c++) {
            unsigned long long hpa = pk2(h1a[c], h1a[c]);
            unsigned long long hpb = pk2(h1b[c], h1b[c]);
            const ulonglong2* wv = (const ulonglong2*)&w2p[c][ch * 4];
            ulonglong2 wa = wv[0], wb = wv[1];
            a01 = fma2(wa.x, hpa, a01);
            a23 = fma2(wa.y, hpa, a23);
            a45 = fma2(wb.x, hpa, a45);
            a67 = fma2(wb.y, hpa, a67);
            b01 = fma2(wa.x, hpb, b01);
            b23 = fma2(wa.y, hpb, b23);
            b45 = fma2(wb.x, hpb, b45);
            b67 = fma2(wb.y, hpb, b67);
        }
        float va[8], vb[8];
        upk2(a01, va[0], va[1]); upk2(a23, va[2], va[3]);
        upk2(a45, va[4], va[5]); upk2(a67, va[6], va[7]);
        upk2(b01, vb[0], vb[1]); upk2(b23, vb[2], vb[3]);
        upk2(b45, vb[4], vb[5]); upk2(b67, vb[6], vb[7]);
        float v[8];
#pragma unroll
        for (int u = 0; u < 8; u++)
            v[u] = fmaxf(lrelu(va[u]), lrelu(vb[u]));
#pragma unroll
        for (int s = 4; s >= 1; s >>= 1) {
#pragma unroll
            for (int u = 0; u < 8; u++)
                v[u] = fmaxf(v[u], __shfl_xor_sync(0xffffffffu, v[u], s));
        }
        if (k == 0) {
#pragma unroll
            for (int u = 0; u < 8; u++) stage[g][ch * 8 + u] = v[u];
        }
    }
    __syncthreads();

    int gq0 = blockIdx.x * 16;
    int b0 = gq0 / NN, n0 = gq0 % NN;
    for (int i = tid; i < 16 * M2; i += 128) {
        int o = i >> 4, gi = i & 15;
        out[((size_t)b0 * M2 + o) * NN + (n0 + gi)] = stage[gi][o];
    }
}

extern "C" void kernel_launch(void* const* d_in, const int* in_sizes, int n_in,
                              void* d_out, int out_size) {
    const float* xyz    = (const float*)d_in[0];
    const float* points = (const float*)d_in[1];
    const float* W0     = (const float*)d_in[2];
    const float* W1     = (const float*)d_in[3];
    const float* W2     = (const float*)d_in[4];
    float* out = (float*)d_out;

    init_kernel<<<(BB * BINS + 1023) / 1024, 1024>>>();
    prep_kernel<<<BB * NN / 128, 128>>>(xyz, points, W0);
    prefix_kernel<<<BB, BINS>>>();
    scatter_kernel<<<BB * NN / 256, 256>>>();

    dim3 g2(NN / 32, BB);
    knnt_kernel<<<g2, KBLK>>>();

    mlp_kernel<<<BB * NN / 16, 128>>>(W0, W1, W2, out);
}

// round 16
// speedup vs baseline: 1.0065x; 1.0065x over previous
#include <cuda_runtime.h>

#define BB 4
#define NN 8192
#define DD 32
#define KNB 16
#define M0 32
#define M1 32
#define M2 64
#define LEAKY 0.1f

#define BINS 1024
#define XMIN (-16.0f)
#define XRANGE 32.0f
#define BINW (XRANGE / (float)BINS)
#define MARG 2e-3f

#define STILE 256
#define NT (NN / STILE)      // 32 tiles per batch
#define RINGN 16
#define KBLK 128             // 32 queries x 4 lanes = 4 warps

__device__ float4 g_xyzw[BB * NN];
__device__ float  g_feat[BB * NN * M0];
__device__ int    g_idx[BB * NN * KNB];

__device__ int    g_bincnt[BB * BINS];
__device__ int    g_bincur[BB * BINS];
__device__ float4 g_s4[BB * NN];
__device__ int    g_sidx[BB * NN];

__device__ __forceinline__ float lrelu(float x) { return x > 0.f ? x : LEAKY * x; }

__device__ __forceinline__ int xbin(float x) {
    int bn = (int)((x - XMIN) * ((float)BINS / XRANGE));
    return min(max(bn, 0), BINS - 1);
}

__device__ __forceinline__ unsigned long long pk2(float lo, float hi) {
    unsigned long long r;
    asm("mov.b64 %0, {%1, %2};" : "=l"(r) : "f"(lo), "f"(hi));
    return r;
}
__device__ __forceinline__ void upk2(unsigned long long v, float& lo, float& hi) {
    asm("mov.b64 {%0, %1}, %2;" : "=f"(lo), "=f"(hi) : "l"(v));
}
__device__ __forceinline__ unsigned long long fma2(unsigned long long a,
                                                   unsigned long long b,
                                                   unsigned long long c) {
    unsigned long long d;
    asm("fma.rn.f32x2 %0, %1, %2, %3;" : "=l"(d) : "l"(a), "l"(b), "l"(c));
    return d;
}

// ---------------------------------------------------------------------------
// Kernel 0: zero histogram counters
// ---------------------------------------------------------------------------
__global__ void init_kernel(void) {
    int i = blockIdx.x * 1024 + threadIdx.x;
    if (i < BB * BINS) g_bincnt[i] = 0;
}

// ---------------------------------------------------------------------------
// Kernel 1: pack xyz; feat = W0[:,3:] @ points; histogram x into bins.
// ---------------------------------------------------------------------------
__global__ void prep_kernel(const float* __restrict__ xyz,
                            const float* __restrict__ points,
                            const float* __restrict__ W0) {
    __shared__ __align__(16) float wfT[DD][M0];
    int tid = threadIdx.x;
    for (int i = tid; i < DD * M0; i += 128) {
        int c = i / M0, o = i % M0;
        wfT[c][o] = W0[o * 35 + 3 + c];
    }
    __syncthreads();

    int gq = blockIdx.x * 128 + tid;
    int b = gq / NN, n = gq % NN;

    const float* xb = xyz + (size_t)b * 3 * NN;
    float x = xb[n], y = xb[NN + n], z = xb[2 * NN + n];
    float sq = fmaf(x, x, fmaf(y, y, z * z));
    g_xyzw[gq] = make_float4(x, y, z, sq);

    atomicAdd(&g_bincnt[b * BINS + xbin(x)], 1);

    float acc[M0];
#pragma unroll
    for (int o = 0; o < M0; o++) acc[o] = 0.f;

    const float* pb = points + (size_t)b * DD * NN + n;
#pragma unroll 4
    for (int c = 0; c < DD; c++) {
        float p = pb[(size_t)c * NN];
        const float4* w4 = (const float4*)wfT[c];
#pragma unroll
        for (int o4 = 0; o4 < M0 / 4; o4++) {
            float4 w = w4[o4];
            acc[o4 * 4 + 0] = fmaf(w.x, p, acc[o4 * 4 + 0]);
            acc[o4 * 4 + 1] = fmaf(w.y, p, acc[o4 * 4 + 1]);
            acc[o4 * 4 + 2] = fmaf(w.z, p, acc[o4 * 4 + 2]);
            acc[o4 * 4 + 3] = fmaf(w.w, p, acc[o4 * 4 + 3]);
        }
    }
    float4* fo = (float4*)(g_feat + (size_t)gq * M0);
#pragma unroll
    for (int o4 = 0; o4 < M0 / 4; o4++)
        fo[o4] = make_float4(acc[o4 * 4 + 0], acc[o4 * 4 + 1],
                             acc[o4 * 4 + 2], acc[o4 * 4 + 3]);
}

// ---------------------------------------------------------------------------
// Kernel 2: parallel per-batch prefix scan
// ---------------------------------------------------------------------------
__global__ void prefix_kernel(void) {
    __shared__ int s[BINS];
    int b = blockIdx.x, t = threadIdx.x;
    int mine = g_bincnt[b * BINS + t];
    s[t] = mine;
    __syncthreads();
    for (int off = 1; off < BINS; off <<= 1) {
        int v = (t >= off) ? s[t - off] : 0;
        __syncthreads();
        s[t] += v;
        __syncthreads();
    }
    g_bincur[b * BINS + t] = s[t] - mine;
}

// ---------------------------------------------------------------------------
// Kernel 3: scatter points into x-bin-sorted arrays
// ---------------------------------------------------------------------------
__global__ void scatter_kernel(void) {
    int gq = blockIdx.x * 256 + threadIdx.x;
    int b = gq / NN, n = gq % NN;
    float4 p = g_xyzw[gq];
    int pos = atomicAdd(&g_bincur[b * BINS + xbin(p.x)], 1);
    g_s4[b * NN + pos] = p;
    g_sidx[b * NN + pos] = n;
}

// ---------------------------------------------------------------------------
// kNN consolidation: ring entries carry (d bits << 32 | global sorted pos).
// Original index fetched by LDG only for candidate inserts. Lex keys
// (flipped d << 32 | orig idx) keep jax top_k tie order exactly.
// ---------------------------------------------------------------------------
__device__ __forceinline__ void consolidate(unsigned long long (&slot)[KNB],
                                            unsigned long long& worstkey,
                                            float& worst_d, int& cnt,
                                            unsigned long long (*ring)[KBLK],
                                            const int* __restrict__ sidx,
                                            int tid) {
#pragma unroll 1
    for (int i = 0; i < cnt; i++) {
        unsigned long long e = ring[i][tid];
        unsigned db = (unsigned)(e >> 32);
        unsigned msk = ((unsigned)((int)db >> 31)) | 0x80000000u;
        unsigned hi = db ^ msk;
        // quick reject on distance bits alone (hi > worst's hi -> skip)
        if (hi <= (unsigned)(worstkey >> 32)) {
            unsigned orig = (unsigned)__ldg(&sidx[(unsigned)e]);
            unsigned long long key = ((unsigned long long)hi << 32) | orig;
            if (key < worstkey) {
#pragma unroll
                for (int m = 0; m < KNB; m++)
                    slot[m] = (slot[m] == worstkey) ? key : slot[m];
                unsigned long long w = slot[0];
#pragma unroll
                for (int m = 1; m < KNB; m++) w = (slot[m] > w) ? slot[m] : w;
                worstkey = w;
            }
        }
    }
    cnt = 0;
    unsigned k32 = (unsigned)(worstkey >> 32);
    unsigned bits = (k32 & 0x80000000u) ? (k32 ^ 0x80000000u) : ~k32;
    worst_d = __uint_as_float(bits);
}

// ---------------------------------------------------------------------------
// Kernel 4: warp-autonomous sorted-window kNN. Warp = 8 consecutive sorted
// queries x 4 lanes; per-warp window expansion via __all_sync consensus.
// NO block barriers in the main loop; candidates read directly via LDG
// (g_s4 per batch = 128KB, L1-resident; warp reads 4 distinct float4 =
// 64B contiguous per group step). grid (N/32, B), block 128 = 4 warps.
// ---------------------------------------------------------------------------
__global__ void __launch_bounds__(KBLK) knnw2_kernel(void) {
    __shared__ unsigned long long ring[RINGN][KBLK];

    int tid = threadIdx.x;
    int b = blockIdx.y;
    int r = tid & 3;
    int rank = blockIdx.x * 32 + (tid >> 2);

    const float4* __restrict__ s4 = g_s4 + (size_t)b * NN;
    const int* __restrict__ sidx = g_sidx + (size_t)b * NN;

    float4 qf = s4[rank];
    int qorig = sidx[rank];
    float nqx = -2.f * qf.x, nqy = -2.f * qf.y, nqz = -2.f * qf.z;
    float qw = qf.w;

    unsigned long long slot[KNB];
#pragma unroll
    for (int m = 0; m < KNB; m++)
        slot[m] = 0xFF80000000000000ull | (unsigned)m;  // flip(+inf) | m
    unsigned long long worstkey = 0xFF80000000000000ull | (KNB - 1);
    float worst_d = __int_as_float(0x7F800000);
    float tp = __int_as_float(0x7F800000);
    int cnt = 0;

    int T0 = rank / STILE;            // warp-uniform (8-query span aligned)
    int tR = T0, tL = T0 - 1;
    bool rightDone = false, leftDone = false;
    bool firstTile = true;

    for (;;) {
        int doScan = -1;

        if (tR < NT) {
            bool prune = false;
            if (!firstTile) {
                float dxlo = __ldg(&s4[tR * STILE].x) - BINW - qf.x;
                prune = (dxlo > 0.f) && (dxlo * dxlo > tp + MARG);
            }
            rightDone = rightDone || prune;
            if (__all_sync(0xffffffffu, rightDone)) tR = NT;
            else { doScan = tR; tR++; }
            firstTile = false;
        }
        if (doScan < 0 && tL >= 0) {
            float dxhi = qf.x - (__ldg(&s4[tL * STILE + STILE - 1].x) + BINW);
            bool prune = (dxhi > 0.f) && (dxhi * dxhi > tp + MARG);
            leftDone = leftDone || prune;
            if (__all_sync(0xffffffffu, leftDone)) tL = -1;
            else { doScan = tL; tL--; }
        }
        if (doScan < 0) break;   // both directions exhausted

        int base = doScan * STILE;
#pragma unroll 1
        for (int j0 = 0; j0 < STILE; j0 += 32) {
#pragma unroll
            for (int u = 0; u < 8; u++) {
                int jl = base + j0 + u * 4 + r;
                float4 c = __ldg(&s4[jl]);
                float d = fmaf(nqx, c.x,
                          fmaf(nqy, c.y, fmaf(nqz, c.z, qw + c.w)));
                // unconditional store, conditional advance (branchless)
                ring[cnt][tid] =
                    ((unsigned long long)__float_as_uint(d) << 32) |
                    (unsigned)jl;
                cnt += (d <= tp) ? 1 : 0;
            }
            // drain at cnt>=9: next group adds <=8 so cnt stays <=16
            if (__ballot_sync(0xffffffffu, cnt >= 9)) {
                consolidate(slot, worstkey, worst_d, cnt, ring, sidx, tid);
                float tt = fminf(worst_d,
                                 __shfl_xor_sync(0xffffffffu, worst_d, 1));
                tt = fminf(tt, __shfl_xor_sync(0xffffffffu, tt, 2));
                tp = tt;
            }
        }
    }
    if (__ballot_sync(0xffffffffu, cnt > 0))
        consolidate(slot, worstkey, worst_d, cnt, ring, sidx, tid);

    // bitonic sort own 16 ascending (lex key order == jax top_k order)
#pragma unroll
    for (int k = 2; k <= KNB; k <<= 1) {
#pragma unroll
        for (int jj = k >> 1; jj > 0; jj >>= 1) {
#pragma unroll
            for (int ii = 0; ii < KNB; ii++) {
                int p = ii ^ jj;
                if (p > ii) {
                    bool up = ((ii & k) == 0);
                    unsigned long long a = slot[ii], bb2 = slot[p];
                    bool sw = (a > bb2) != up;
                    slot[ii] = sw ? bb2 : a;
                    slot[p] = sw ? a : bb2;
                }
            }
        }
    }

    // 2 butterfly merge rounds across the 4 lanes (xor 1, 2)
#pragma unroll
    for (int step = 1; step <= 2; step <<= 1) {
        unsigned long long other[KNB];
#pragma unroll
        for (int ii = 0; ii < KNB; ii++)
            other[ii] = __shfl_xor_sync(0xffffffffu, slot[ii], step);
        unsigned long long c[KNB];
#pragma unroll
        for (int ii = 0; ii < KNB; ii++) {
            unsigned long long bv = other[KNB - 1 - ii];
            c[ii] = (slot[ii] < bv) ? slot[ii] : bv;
        }
#pragma unroll
        for (int jj = KNB / 2; jj > 0; jj >>= 1) {
#pragma unroll
            for (int ii = 0; ii < KNB; ii++) {
                if ((ii & jj) == 0) {
                    int p = ii | jj;
                    unsigned long long a = c[ii], bb2 = c[p];
                    bool sw = (a > bb2);
                    c[ii] = sw ? bb2 : a;
                    c[p] = sw ? a : bb2;
                }
            }
        }
#pragma unroll
        for (int ii = 0; ii < KNB; ii++) slot[ii] = c[ii];
    }

    int4* op = (int4*)(g_idx + ((size_t)b * NN + qorig) * KNB + 4 * r);
    *op = make_int4((int)(unsigned)slot[4 * r + 0],
                    (int)(unsigned)slot[4 * r + 1],
                    (int)(unsigned)slot[4 * r + 2],
                    (int)(unsigned)slot[4 * r + 3]);
}

// ---------------------------------------------------------------------------
// Kernel 5: gather + MLP + max (R15 version, measured ~= R13's 100us).
// block 128 = 16 queries x 8 lanes; 2 neighbors per lane; all three layers
// share their smem weight loads across both neighbors.
// ---------------------------------------------------------------------------
__global__ void __launch_bounds__(128) mlp_kernel(const float* __restrict__ W0,
                                                  const float* __restrict__ W1,
                                                  const float* __restrict__ W2,
                                                  float* __restrict__ out) {
    __shared__ __align__(16) float w0x[M0][4];
    __shared__ __align__(16) unsigned long long w1p[M0][M1 / 2];
    __shared__ __align__(16) unsigned long long w2p[M1][M2 / 2];
    __shared__ float stage[16][M2];

    int tid = threadIdx.x;
    for (int i = tid; i < M0 * 4; i += 128) {
        int o = i / 4, c = i % 4;
        w0x[o][c] = (c < 3) ? W0[o * 35 + c] : 0.f;
    }
    for (int i = tid; i < M0 * (M1 / 2); i += 128) {
        int c = i / (M1 / 2), p = i % (M1 / 2);
        w1p[c][p] = pk2(W1[(2 * p) * M0 + c], W1[(2 * p + 1) * M0 + c]);
    }
    for (int i = tid; i < M1 * (M2 / 2); i += 128) {
        int c = i / (M2 / 2), p = i % (M2 / 2);
        w2p[c][p] = pk2(W2[(2 * p) * M1 + c], W2[(2 * p + 1) * M1 + c]);
    }
    __syncthreads();

    int g = tid >> 3, k = tid & 7;
    int gq = blockIdx.x * 16 + g;
    int b = gq / NN;
    float4 qf = g_xyzw[gq];

    int ja = g_idx[(size_t)gq * KNB + k];
    int jb = g_idx[(size_t)gq * KNB + k + 8];
    float4 cfa = g_xyzw[b * NN + ja];
    float4 cfb = g_xyzw[b * NN + jb];
    float rxa = cfa.x - qf.x, rya = cfa.y - qf.y, rza = cfa.z - qf.z;
    float rxb = cfb.x - qf.x, ryb = cfb.y - qf.y, rzb = cfb.z - qf.z;

    float h0a[M0], h0b[M0];
    const float4* fga = (const float4*)(g_feat + ((size_t)b * NN + ja) * M0);
    const float4* fgb = (const float4*)(g_feat + ((size_t)b * NN + jb) * M0);
#pragma unroll
    for (int o4 = 0; o4 < M0 / 4; o4++) {
        float4 fa = fga[o4];
        float4 fb = fgb[o4];
        float fva[4] = {fa.x, fa.y, fa.z, fa.w};
        float fvb[4] = {fb.x, fb.y, fb.z, fb.w};
#pragma unroll
        for (int u = 0; u < 4; u++) {
            float4 w = *(const float4*)w0x[o4 * 4 + u];
            h0a[o4 * 4 + u] =
                lrelu(fmaf(w.x, rxa, fmaf(w.y, rya, fmaf(w.z, rza, fva[u]))));
            h0b[o4 * 4 + u] =
                lrelu(fmaf(w.x, rxb, fmaf(w.y, ryb, fmaf(w.z, rzb, fvb[u]))));
        }
    }

    unsigned long long acc1a[M1 / 2], acc1b[M1 / 2];
#pragma unroll
    for (int p = 0; p < M1 / 2; p++) { acc1a[p] = 0ull; acc1b[p] = 0ull; }
#pragma unroll
    for (int c = 0; c < M0; c++) {
        unsigned long long hpa = pk2(h0a[c], h0a[c]);
        unsigned long long hpb = pk2(h0b[c], h0b[c]);
        const ulonglong2* wv = (const ulonglong2*)w1p[c];
#pragma unroll
        for (int p2 = 0; p2 < M1 / 4; p2++) {
            ulonglong2 w = wv[p2];
            acc1a[2 * p2 + 0] = fma2(w.x, hpa, acc1a[2 * p2 + 0]);
            acc1a[2 * p2 + 1] = fma2(w.y, hpa, acc1a[2 * p2 + 1]);
            acc1b[2 * p2 + 0] = fma2(w.x, hpb, acc1b[2 * p2 + 0]);
            acc1b[2 * p2 + 1] = fma2(w.y, hpb, acc1b[2 * p2 + 1]);
        }
    }
    float h1a[M1], h1b[M1];
#pragma unroll
    for (int p = 0; p < M1 / 2; p++) {
        float a, bv;
        upk2(acc1a[p], a, bv);
        h1a[2 * p + 0] = lrelu(a);
        h1a[2 * p + 1] = lrelu(bv);
        upk2(acc1b[p], a, bv);
        h1b[2 * p + 0] = lrelu(a);
        h1b[2 * p + 1] = lrelu(bv);
    }

#pragma unroll 1
    for (int ch = 0; ch < M2 / 8; ch++) {
        unsigned long long a01 = 0ull, a23 = 0ull, a45 = 0ull, a67 = 0ull;
        unsigned long long b01 = 0ull, b23 = 0ull, b45 = 0ull, b67 = 0ull;
#pragma unroll
        for (int c = 0; c < M1; c++) {
            unsigned long long hpa = pk2(h1a[c], h1a[c]);
            unsigned long long hpb = pk2(h1b[c], h1b[c]);
            const ulonglong2* wv = (const ulonglong2*)&w2p[c][ch * 4];
            ulonglong2 wa = wv[0], wb = wv[1];
            a01 = fma2(wa.x, hpa, a01);
            a23 = fma2(wa.y, hpa, a23);
            a45 = fma2(wb.x, hpa, a45);
            a67 = fma2(wb.y, hpa, a67);
            b01 = fma2(wa.x, hpb, b01);
            b23 = fma2(wa.y, hpb, b23);
            b45 = fma2(wb.x, hpb, b45);
            b67 = fma2(wb.y, hpb, b67);
        }
        float va[8], vb[8];
        upk2(a01, va[0], va[1]); upk2(a23, va[2], va[3]);
        upk2(a45, va[4], va[5]); upk2(a67, va[6], va[7]);
        upk2(b01, vb[0], vb[1]); upk2(b23, vb[2], vb[3]);
        upk2(b45, vb[4], vb[5]); upk2(b67, vb[6], vb[7]);
        float v[8];
#pragma unroll
        for (int u = 0; u < 8; u++)
            v[u] = fmaxf(lrelu(va[u]), lrelu(vb[u]));
#pragma unroll
        for (int s = 4; s >= 1; s >>= 1) {
#pragma unroll
            for (int u = 0; u < 8; u++)
                v[u] = fmaxf(v[u], __shfl_xor_sync(0xffffffffu, v[u], s));
        }
        if (k == 0) {
#pragma unroll
            for (int u = 0; u < 8; u++) stage[g][ch * 8 + u] = v[u];
        }
    }
    __syncthreads();

    int gq0 = blockIdx.x * 16;
    int b0 = gq0 / NN, n0 = gq0 % NN;
    for (int i = tid; i < 16 * M2; i += 128) {
        int o = i >> 4, gi = i & 15;
        out[((size_t)b0 * M2 + o) * NN + (n0 + gi)] = stage[gi][o];
    }
}

extern "C" void kernel_launch(void* const* d_in, const int* in_sizes, int n_in,
                              void* d_out, int out_size) {
    const float* xyz    = (const float*)d_in[0];
    const float* points = (const float*)d_in[1];
    const float* W0     = (const float*)d_in[2];
    const float* W1     = (const float*)d_in[3];
    const float* W2     = (const float*)d_in[4];
    float* out = (float*)d_out;

    init_kernel<<<(BB * BINS + 1023) / 1024, 1024>>>();
    prep_kernel<<<BB * NN / 128, 128>>>(xyz, points, W0);
    prefix_kernel<<<BB, BINS>>>();
    scatter_kernel<<<BB * NN / 256, 256>>>();

    dim3 g2(NN / 32, BB);
    knnw2_kernel<<<g2, KBLK>>>();

    mlp_kernel<<<BB * NN / 16, 128>>>(W0, W1, W2, out);
}

// round 17
// speedup vs baseline: 1.0821x; 1.0752x over previous
#include <cuda_runtime.h>

#define BB 4
#define NN 8192
#define DD 32
#define KNB 16
#define M0 32
#define M1 32
#define M2 64
#define LEAKY 0.1f

#define BINS 1024
#define XMIN (-16.0f)
#define XRANGE 32.0f
#define BINW (XRANGE / (float)BINS)
#define MARG 2e-3f

#define STILE 256
#define NT (NN / STILE)      // 32 tiles per batch
#define RINGN 24
#define KBLK 128             // 32 queries x 4 lanes = 4 warps

__device__ float4 g_xyzw[BB * NN];
__device__ float  g_feat[BB * NN * M0];
__device__ int    g_idx[BB * NN * KNB];

__device__ float4 g_s4[BB * NN];
__device__ int    g_sidx[BB * NN];

__device__ __forceinline__ float lrelu(float x) { return x > 0.f ? x : LEAKY * x; }

__device__ __forceinline__ int xbin(float x) {
    int bn = (int)((x - XMIN) * ((float)BINS / XRANGE));
    return min(max(bn, 0), BINS - 1);
}

__device__ __forceinline__ unsigned long long pk2(float lo, float hi) {
    unsigned long long r;
    asm("mov.b64 %0, {%1, %2};" : "=l"(r) : "f"(lo), "f"(hi));
    return r;
}
__device__ __forceinline__ void upk2(unsigned long long v, float& lo, float& hi) {
    asm("mov.b64 {%0, %1}, %2;" : "=f"(lo), "=f"(hi) : "l"(v));
}
__device__ __forceinline__ unsigned long long fma2(unsigned long long a,
                                                   unsigned long long b,
                                                   unsigned long long c) {
    unsigned long long d;
    asm("fma.rn.f32x2 %0, %1, %2, %3;" : "=l"(d) : "l"(a), "l"(b), "l"(c));
    return d;
}

// flip float bits to monotone unsigned (ascending order == ascending d)
__device__ __forceinline__ unsigned flipf(unsigned db) {
    unsigned msk = ((unsigned)((int)db >> 31)) | 0x80000000u;
    return db ^ msk;
}

// ---------------------------------------------------------------------------
// Kernel 1: pack xyz; feat = W0[:,3:] @ points. (no histogram here anymore)
// ---------------------------------------------------------------------------
__global__ void prep_kernel(const float* __restrict__ xyz,
                            const float* __restrict__ points,
                            const float* __restrict__ W0) {
    __shared__ __align__(16) float wfT[DD][M0];
    int tid = threadIdx.x;
    for (int i = tid; i < DD * M0; i += 128) {
        int c = i / M0, o = i % M0;
        wfT[c][o] = W0[o * 35 + 3 + c];
    }
    __syncthreads();

    int gq = blockIdx.x * 128 + tid;
    int b = gq / NN, n = gq % NN;

    const float* xb = xyz + (size_t)b * 3 * NN;
    float x = xb[n], y = xb[NN + n], z = xb[2 * NN + n];
    float sq = fmaf(x, x, fmaf(y, y, z * z));
    g_xyzw[gq] = make_float4(x, y, z, sq);

    float acc[M0];
#pragma unroll
    for (int o = 0; o < M0; o++) acc[o] = 0.f;

    const float* pb = points + (size_t)b * DD * NN + n;
#pragma unroll 4
    for (int c = 0; c < DD; c++) {
        float p = pb[(size_t)c * NN];
        const float4* w4 = (const float4*)wfT[c];
#pragma unroll
        for (int o4 = 0; o4 < M0 / 4; o4++) {
            float4 w = w4[o4];
            acc[o4 * 4 + 0] = fmaf(w.x, p, acc[o4 * 4 + 0]);
            acc[o4 * 4 + 1] = fmaf(w.y, p, acc[o4 * 4 + 1]);
            acc[o4 * 4 + 2] = fmaf(w.z, p, acc[o4 * 4 + 2]);
            acc[o4 * 4 + 3] = fmaf(w.w, p, acc[o4 * 4 + 3]);
        }
    }
    float4* fo = (float4*)(g_feat + (size_t)gq * M0);
#pragma unroll
    for (int o4 = 0; o4 < M0 / 4; o4++)
        fo[o4] = make_float4(acc[o4 * 4 + 0], acc[o4 * 4 + 1],
                             acc[o4 * 4 + 2], acc[o4 * 4 + 3]);
}

// ---------------------------------------------------------------------------
// Kernel 2: fused histogram + prefix + scatter. 1 block (1024 thr) / batch.
// Within-bin order is atomic-nondeterministic; result exactness holds
// because the kNN top-16 is computed on order-independent global lex keys.
// ---------------------------------------------------------------------------
__global__ void __launch_bounds__(BINS) sort_kernel(void) {
    __shared__ int s[BINS];
    __shared__ int cur[BINS];
    int b = blockIdx.x, t = threadIdx.x;

    s[t] = 0;
    __syncthreads();

    for (int i = t; i < NN; i += BINS)
        atomicAdd(&s[xbin(g_xyzw[b * NN + i].x)], 1);
    __syncthreads();

    int mine = s[t];
    __syncthreads();
    for (int off = 1; off < BINS; off <<= 1) {
        int v = (t >= off) ? s[t - off] : 0;
        __syncthreads();
        s[t] += v;
        __syncthreads();
    }
    cur[t] = s[t] - mine;   // exclusive prefix
    __syncthreads();

    for (int i = t; i < NN; i += BINS) {
        float4 p = g_xyzw[b * NN + i];
        int pos = atomicAdd(&cur[xbin(p.x)], 1);
        g_s4[b * NN + pos] = p;
        g_sidx[b * NN + pos] = i;
    }
}

// ---------------------------------------------------------------------------
// kNN consolidation: ring entries carry (d bits << 32 | global sorted pos).
// Quick-reject on distance bits; original idx via LDG only for candidates.
// ---------------------------------------------------------------------------
__device__ __forceinline__ void consolidate(unsigned long long (&slot)[KNB],
                                            unsigned long long& worstkey,
                                            float& worst_d, int& cnt,
                                            unsigned long long (*ring)[KBLK],
                                            const int* __restrict__ sidx,
                                            int tid) {
#pragma unroll 1
    for (int i = 0; i < cnt; i++) {
        unsigned long long e = ring[i][tid];
        unsigned hi = flipf((unsigned)(e >> 32));
        if (hi <= (unsigned)(worstkey >> 32)) {
            unsigned orig = (unsigned)__ldg(&sidx[(unsigned)e]);
            unsigned long long key = ((unsigned long long)hi << 32) | orig;
            if (key < worstkey) {
#pragma unroll
                for (int m = 0; m < KNB; m++)
                    slot[m] = (slot[m] == worstkey) ? key : slot[m];
                unsigned long long w = slot[0];
#pragma unroll
                for (int m = 1; m < KNB; m++) w = (slot[m] > w) ? slot[m] : w;
                worstkey = w;
            }
        }
    }
    cnt = 0;
    unsigned k32 = (unsigned)(worstkey >> 32);
    unsigned bits = (k32 & 0x80000000u) ? (k32 ^ 0x80000000u) : ~k32;
    worst_d = __uint_as_float(bits);
}

// ---------------------------------------------------------------------------
// Kernel 3: warp-autonomous sorted-window kNN with WARM START.
// Warp = 8 consecutive sorted queries x 4 lanes. Each lane's slots are
// initialized directly from its first 16 scanned candidates (no insert
// storm), making tp finite immediately. Drains at cnt>=17 (ring 24 rows).
// grid (N/32, B), block 128 = 4 warps. No block barriers in main loop.
// ---------------------------------------------------------------------------
__global__ void __launch_bounds__(KBLK) knnw2_kernel(void) {
    __shared__ unsigned long long ring[RINGN][KBLK];

    int tid = threadIdx.x;
    int b = blockIdx.y;
    int r = tid & 3;
    int rank = blockIdx.x * 32 + (tid >> 2);

    const float4* __restrict__ s4 = g_s4 + (size_t)b * NN;
    const int* __restrict__ sidx = g_sidx + (size_t)b * NN;

    float4 qf = s4[rank];
    int qorig = sidx[rank];
    float nqx = -2.f * qf.x, nqy = -2.f * qf.y, nqz = -2.f * qf.z;
    float qw = qf.w;

    int T0 = rank / STILE;            // warp-uniform
    int tbase = T0 * STILE;

    // ---- WARM START: fill slots directly from first 16 lane candidates ----
    unsigned long long slot[KNB];
#pragma unroll
    for (int g2 = 0; g2 < 2; g2++) {
#pragma unroll
        for (int u = 0; u < 8; u++) {
            int jl = tbase + g2 * 32 + u * 4 + r;
            float4 c = __ldg(&s4[jl]);
            float d = fmaf(nqx, c.x, fmaf(nqy, c.y, fmaf(nqz, c.z, qw + c.w)));
            unsigned orig = (unsigned)__ldg(&sidx[jl]);
            slot[g2 * 8 + u] =
                ((unsigned long long)flipf(__float_as_uint(d)) << 32) | orig;
        }
    }
    unsigned long long worstkey = slot[0];
#pragma unroll
    for (int m = 1; m < KNB; m++)
        worstkey = (slot[m] > worstkey) ? slot[m] : worstkey;
    float worst_d;
    {
        unsigned k32 = (unsigned)(worstkey >> 32);
        unsigned bits = (k32 & 0x80000000u) ? (k32 ^ 0x80000000u) : ~k32;
        worst_d = __uint_as_float(bits);
    }
    float tp = fminf(worst_d, __shfl_xor_sync(0xffffffffu, worst_d, 1));
    tp = fminf(tp, __shfl_xor_sync(0xffffffffu, tp, 2));
    int cnt = 0;

    // ---- remainder of own tile (j0 from 64) ----
#pragma unroll 1
    for (int j0 = 64; j0 < STILE; j0 += 32) {
#pragma unroll
        for (int u = 0; u < 8; u++) {
            int jl = tbase + j0 + u * 4 + r;
            float4 c = __ldg(&s4[jl]);
            float d = fmaf(nqx, c.x, fmaf(nqy, c.y, fmaf(nqz, c.z, qw + c.w)));
            ring[cnt][tid] =
                ((unsigned long long)__float_as_uint(d) << 32) | (unsigned)jl;
            cnt += (d <= tp) ? 1 : 0;
        }
        if (__ballot_sync(0xffffffffu, cnt >= 17)) {
            consolidate(slot, worstkey, worst_d, cnt, ring, sidx, tid);
            float tt = fminf(worst_d, __shfl_xor_sync(0xffffffffu, worst_d, 1));
            tt = fminf(tt, __shfl_xor_sync(0xffffffffu, tt, 2));
            tp = tt;
        }
    }

    // ---- expand right then left, per-warp consensus pruning ----
    int tR = T0 + 1, tL = T0 - 1;
    bool rightDone = false, leftDone = false;

    for (;;) {
        int doScan = -1;

        if (tR < NT) {
            float dxlo = __ldg(&s4[tR * STILE].x) - BINW - qf.x;
            bool prune = (dxlo > 0.f) && (dxlo * dxlo > tp + MARG);
            rightDone = rightDone || prune;
            if (__all_sync(0xffffffffu, rightDone)) tR = NT;
            else { doScan = tR; tR++; }
        }
        if (doScan < 0 && tL >= 0) {
            float dxhi = qf.x - (__ldg(&s4[tL * STILE + STILE - 1].x) + BINW);
            bool prune = (dxhi > 0.f) && (dxhi * dxhi > tp + MARG);
            leftDone = leftDone || prune;
            if (__all_sync(0xffffffffu, leftDone)) tL = -1;
            else { doScan = tL; tL--; }
        }
        if (doScan < 0) break;

        int base = doScan * STILE;
#pragma unroll 1
        for (int j0 = 0; j0 < STILE; j0 += 32) {
#pragma unroll
            for (int u = 0; u < 8; u++) {
                int jl = base + j0 + u * 4 + r;
                float4 c = __ldg(&s4[jl]);
                float d = fmaf(nqx, c.x,
                          fmaf(nqy, c.y, fmaf(nqz, c.z, qw + c.w)));
                ring[cnt][tid] =
                    ((unsigned long long)__float_as_uint(d) << 32) |
                    (unsigned)jl;
                cnt += (d <= tp) ? 1 : 0;
            }
            if (__ballot_sync(0xffffffffu, cnt >= 17)) {
                consolidate(slot, worstkey, worst_d, cnt, ring, sidx, tid);
                float tt = fminf(worst_d,
                                 __shfl_xor_sync(0xffffffffu, worst_d, 1));
                tt = fminf(tt, __shfl_xor_sync(0xffffffffu, tt, 2));
                tp = tt;
            }
        }
    }
    if (__ballot_sync(0xffffffffu, cnt > 0))
        consolidate(slot, worstkey, worst_d, cnt, ring, sidx, tid);

    // bitonic sort own 16 ascending (lex key order == jax top_k order)
#pragma unroll
    for (int k = 2; k <= KNB; k <<= 1) {
#pragma unroll
        for (int jj = k >> 1; jj > 0; jj >>= 1) {
#pragma unroll
            for (int ii = 0; ii < KNB; ii++) {
                int p = ii ^ jj;
                if (p > ii) {
                    bool up = ((ii & k) == 0);
                    unsigned long long a = slot[ii], bb2 = slot[p];
                    bool sw = (a > bb2) != up;
                    slot[ii] = sw ? bb2 : a;
                    slot[p] = sw ? a : bb2;
                }
            }
        }
    }

    // 2 butterfly merge rounds across the 4 lanes (xor 1, 2)
#pragma unroll
    for (int step = 1; step <= 2; step <<= 1) {
        unsigned long long other[KNB];
#pragma unroll
        for (int ii = 0; ii < KNB; ii++)
            other[ii] = __shfl_xor_sync(0xffffffffu, slot[ii], step);
        unsigned long long c[KNB];
#pragma unroll
        for (int ii = 0; ii < KNB; ii++) {
            unsigned long long bv = other[KNB - 1 - ii];
            c[ii] = (slot[ii] < bv) ? slot[ii] : bv;
        }
#pragma unroll
        for (int jj = KNB / 2; jj > 0; jj >>= 1) {
#pragma unroll
            for (int ii = 0; ii < KNB; ii++) {
                if ((ii & jj) == 0) {
                    int p = ii | jj;
                    unsigned long long a = c[ii], bb2 = c[p];
                    bool sw = (a > bb2);
                    c[ii] = sw ? bb2 : a;
                    c[p] = sw ? a : bb2;
                }
            }
        }
#pragma unroll
        for (int ii = 0; ii < KNB; ii++) slot[ii] = c[ii];
    }

    int4* op = (int4*)(g_idx + ((size_t)b * NN + qorig) * KNB + 4 * r);
    *op = make_int4((int)(unsigned)slot[4 * r + 0],
                    (int)(unsigned)slot[4 * r + 1],
                    (int)(unsigned)slot[4 * r + 2],
                    (int)(unsigned)slot[4 * r + 3]);
}

// ---------------------------------------------------------------------------
// Kernel 4: gather + MLP + max (unchanged; ~100us). block 128 = 16 queries
// x 8 lanes; 2 neighbors per lane; all three layers share smem weight loads.
// ---------------------------------------------------------------------------
__global__ void __launch_bounds__(128) mlp_kernel(const float* __restrict__ W0,
                                                  const float* __restrict__ W1,
                                                  const float* __restrict__ W2,
                                                  float* __restrict__ out) {
    __shared__ __align__(16) float w0x[M0][4];
    __shared__ __align__(16) unsigned long long w1p[M0][M1 / 2];
    __shared__ __align__(16) unsigned long long w2p[M1][M2 / 2];
    __shared__ float stage[16][M2];

    int tid = threadIdx.x;
    for (int i = tid; i < M0 * 4; i += 128) {
        int o = i / 4, c = i % 4;
        w0x[o][c] = (c < 3) ? W0[o * 35 + c] : 0.f;
    }
    for (int i = tid; i < M0 * (M1 / 2); i += 128) {
        int c = i / (M1 / 2), p = i % (M1 / 2);
        w1p[c][p] = pk2(W1[(2 * p) * M0 + c], W1[(2 * p + 1) * M0 + c]);
    }
    for (int i = tid; i < M1 * (M2 / 2); i += 128) {
        int c = i / (M2 / 2), p = i % (M2 / 2);
        w2p[c][p] = pk2(W2[(2 * p) * M1 + c], W2[(2 * p + 1) * M1 + c]);
    }
    __syncthreads();

    int g = tid >> 3, k = tid & 7;
    int gq = blockIdx.x * 16 + g;
    int b = gq / NN;
    float4 qf = g_xyzw[gq];

    int ja = g_idx[(size_t)gq * KNB + k];
    int jb = g_idx[(size_t)gq * KNB + k + 8];
    float4 cfa = g_xyzw[b * NN + ja];
    float4 cfb = g_xyzw[b * NN + jb];
    float rxa = cfa.x - qf.x, rya = cfa.y - qf.y, rza = cfa.z - qf.z;
    float rxb = cfb.x - qf.x, ryb = cfb.y - qf.y, rzb = cfb.z - qf.z;

    float h0a[M0], h0b[M0];
    const float4* fga = (const float4*)(g_feat + ((size_t)b * NN + ja) * M0);
    const float4* fgb = (const float4*)(g_feat + ((size_t)b * NN + jb) * M0);
#pragma unroll
    for (int o4 = 0; o4 < M0 / 4; o4++) {
        float4 fa = fga[o4];
        float4 fb = fgb[o4];
        float fva[4] = {fa.x, fa.y, fa.z, fa.w};
        float fvb[4] = {fb.x, fb.y, fb.z, fb.w};
#pragma unroll
        for (int u = 0; u < 4; u++) {
            float4 w = *(const float4*)w0x[o4 * 4 + u];
            h0a[o4 * 4 + u] =
                lrelu(fmaf(w.x, rxa, fmaf(w.y, rya, fmaf(w.z, rza, fva[u]))));
            h0b[o4 * 4 + u] =
                lrelu(fmaf(w.x, rxb, fmaf(w.y, ryb, fmaf(w.z, rzb, fvb[u]))));
        }
    }

    unsigned long long acc1a[M1 / 2], acc1b[M1 / 2];
#pragma unroll
    for (int p = 0; p < M1 / 2; p++) { acc1a[p] = 0ull; acc1b[p] = 0ull; }
#pragma unroll
    for (int c = 0; c < M0; c++) {
        unsigned long long hpa = pk2(h0a[c], h0a[c]);
        unsigned long long hpb = pk2(h0b[c], h0b[c]);
        const ulonglong2* wv = (const ulonglong2*)w1p[c];
#pragma unroll
        for (int p2 = 0; p2 < M1 / 4; p2++) {
            ulonglong2 w = wv[p2];
            acc1a[2 * p2 + 0] = fma2(w.x, hpa, acc1a[2 * p2 + 0]);
            acc1a[2 * p2 + 1] = fma2(w.y, hpa, acc1a[2 * p2 + 1]);
            acc1b[2 * p2 + 0] = fma2(w.x, hpb, acc1b[2 * p2 + 0]);
            acc1b[2 * p2 + 1] = fma2(w.y, hpb, acc1b[2 * p2 + 1]);
        }
    }
    float h1a[M1], h1b[M1];
#pragma unroll
    for (int p = 0; p < M1 / 2; p++) {
        float a, bv;
        upk2(acc1a[p], a, bv);
        h1a[2 * p + 0] = lrelu(a);
        h1a[2 * p + 1] = lrelu(bv);
        upk2(acc1b[p], a, bv);
        h1b[2 * p + 0] = lrelu(a);
        h1b[2 * p + 1] = lrelu(bv);
    }

#pragma unroll 1
    for (int ch = 0; ch < M2 / 8; ch++) {
        unsigned long long a01 = 0ull, a23 = 0ull, a45 = 0ull, a67 = 0ull;
        unsigned long long b01 = 0ull, b23 = 0ull, b45 = 0ull, b67 = 0ull;
#pragma unroll
        for (int c = 0; c < M1; c++) {
            unsigned long long hpa = pk2(h1a[c], h1a[c]);
            unsigned long long hpb = pk2(h1b[c], h1b[c]);
            const ulonglong2* wv = (const ulonglong2*)&w2p[c][ch * 4];
            ulonglong2 wa = wv[0], wb = wv[1];
            a01 = fma2(wa.x, hpa, a01);
            a23 = fma2(wa.y, hpa, a23);
            a45 = fma2(wb.x, hpa, a45);
            a67 = fma2(wb.y, hpa, a67);
            b01 = fma2(wa.x, hpb, b01);
            b23 = fma2(wa.y, hpb, b23);
            b45 = fma2(wb.x, hpb, b45);
            b67 = fma2(wb.y, hpb, b67);
        }
        float va[8], vb[8];
        upk2(a01, va[0], va[1]); upk2(a23, va[2], va[3]);
        upk2(a45, va[4], va[5]); upk2(a67, va[6], va[7]);
        upk2(b01, vb[0], vb[1]); upk2(b23, vb[2], vb[3]);
        upk2(b45, vb[4], vb[5]); upk2(b67, vb[6], vb[7]);
        float v[8];
#pragma unroll
        for (int u = 0; u < 8; u++)
            v[u] = fmaxf(lrelu(va[u]), lrelu(vb[u]));
#pragma unroll
        for (int s = 4; s >= 1; s >>= 1) {
#pragma unroll
            for (int u = 0; u < 8; u++)
                v[u] = fmaxf(v[u], __shfl_xor_sync(0xffffffffu, v[u], s));
        }
        if (k == 0) {
#pragma unroll
            for (int u = 0; u < 8; u++) stage[g][ch * 8 + u] = v[u];
        }
    }
    __syncthreads();

    int gq0 = blockIdx.x * 16;
    int b0 = gq0 / NN, n0 = gq0 % NN;
    for (int i = tid; i < 16 * M2; i += 128) {
        int o = i >> 4, gi = i & 15;
        out[((size_t)b0 * M2 + o) * NN + (n0 + gi)] = stage[gi][o];
    }
}

extern "C" void kernel_launch(void* const* d_in, const int* in_sizes, int n_in,
                              void* d_out, int out_size) {
    const float* xyz    = (const float*)d_in[0];
    const float* points = (const float*)d_in[1];
    const float* W0     = (const float*)d_in[2];
    const float* W1     = (const float*)d_in[3];
    const float* W2     = (const float*)d_in[4];
    float* out = (float*)d_out;

    prep_kernel<<<BB * NN / 128, 128>>>(xyz, points, W0);

    sort_kernel<<<BB, BINS>>>();

    dim3 g2(NN / 32, BB);
    knnw2_kernel<<<g2, KBLK>>>();

    mlp_kernel<<<BB * NN / 16, 128>>>(W0, W1, W2, out);
}